// round 2
// baseline (speedup 1.0000x reference)
#include <cuda_runtime.h>
#include <cuda_bf16.h>
#include <math.h>

#define NUM_SEG 16
#define CHAN 128
#define HID 32

// Pass-1 grid: 148 SMs * 7 blocks (32KB smem each -> 7 blocks/SM)
#define NBLK1 1036
#define THR1 128   // 4 warps/block

// Modulate grid
#define NBLK3 1184
#define THR3 256

// Scratch (static device globals: allocation-free)
__device__ float g_part[(size_t)NBLK1 * NUM_SEG * CHAN];  // per-block partial sums
__device__ float g_cntp[NBLK1 * NUM_SEG];                 // per-block partial counts
__device__ float g_gate[NUM_SEG * CHAN];                  // final gates

// ---------------------------------------------------------------------------
// Kernel 1: per-block segment sums with warp-private smem accumulators.
// Warp handles one row per iteration: lane owns channels [4L, 4L+3] (float4).
// Non-atomic RMW into the warp's private 8KB region. Counts in registers:
// lane L counts occurrences of segment L.
// ---------------------------------------------------------------------------
__global__ void __launch_bounds__(THR1) seg_sum_kernel(
    const float* __restrict__ x, const int* __restrict__ idx, int N)
{
    __shared__ float4 s_acc[4 * NUM_SEG * 32];   // 4 warps * 16 seg * 32 float4 = 32KB
    __shared__ float  s_cnt[4 * NUM_SEG];

    const int tid  = threadIdx.x;
    const int lane = tid & 31;
    const int w    = tid >> 5;

    float4* buf = s_acc + w * (NUM_SEG * 32);

    #pragma unroll
    for (int i = tid; i < 4 * NUM_SEG * 32; i += THR1)
        s_acc[i] = make_float4(0.f, 0.f, 0.f, 0.f);
    __syncthreads();

    const int gw = blockIdx.x * 4 + w;      // global warp id
    const int nw = NBLK1 * 4;               // total warps
    const float4* X = (const float4*)x;

    int cnt = 0;
    int r = gw;
    // 4-deep software pipeline: batch the loads so ptxas front-loads LDGs (MLP)
    for (; r + 3 * nw < N; r += 4 * nw) {
        int s0 = __ldg(idx + r);
        int s1 = __ldg(idx + r + nw);
        int s2 = __ldg(idx + r + 2 * nw);
        int s3 = __ldg(idx + r + 3 * nw);
        float4 v0 = X[(size_t)r * 32 + lane];
        float4 v1 = X[(size_t)(r + nw) * 32 + lane];
        float4 v2 = X[(size_t)(r + 2 * nw) * 32 + lane];
        float4 v3 = X[(size_t)(r + 3 * nw) * 32 + lane];
        cnt += (s0 == lane) + (s1 == lane) + (s2 == lane) + (s3 == lane);

        float4* p; float4 a;
        p = buf + s0 * 32 + lane; a = *p;
        a.x += v0.x; a.y += v0.y; a.z += v0.z; a.w += v0.w; *p = a;
        p = buf + s1 * 32 + lane; a = *p;
        a.x += v1.x; a.y += v1.y; a.z += v1.z; a.w += v1.w; *p = a;
        p = buf + s2 * 32 + lane; a = *p;
        a.x += v2.x; a.y += v2.y; a.z += v2.z; a.w += v2.w; *p = a;
        p = buf + s3 * 32 + lane; a = *p;
        a.x += v3.x; a.y += v3.y; a.z += v3.z; a.w += v3.w; *p = a;
    }
    for (; r < N; r += nw) {
        int s = __ldg(idx + r);
        float4 v = X[(size_t)r * 32 + lane];
        cnt += (s == lane);
        float4* p = buf + s * 32 + lane;
        float4 a = *p;
        a.x += v.x; a.y += v.y; a.z += v.z; a.w += v.w; *p = a;
    }

    if (lane < NUM_SEG) s_cnt[w * NUM_SEG + lane] = (float)cnt;
    __syncthreads();

    // Block-level reduce 4 warp regions -> write per-block partials to GMEM
    const float* sa = (const float*)s_acc;
    const int R = NUM_SEG * CHAN;  // 2048 floats per region
    #pragma unroll 4
    for (int i = tid; i < R; i += THR1) {
        float v = sa[i] + sa[R + i] + sa[2 * R + i] + sa[3 * R + i];
        g_part[(size_t)blockIdx.x * R + i] = v;
    }
    if (tid < NUM_SEG) {
        g_cntp[blockIdx.x * NUM_SEG + tid] =
            s_cnt[tid] + s_cnt[NUM_SEG + tid] + s_cnt[2 * NUM_SEG + tid] + s_cnt[3 * NUM_SEG + tid];
    }
}

// ---------------------------------------------------------------------------
// Kernel 2: reduce partials + SE MLP.  Grid = 16 blocks (one per segment),
// 128 threads (one per channel).
// ---------------------------------------------------------------------------
__global__ void __launch_bounds__(CHAN) reduce_mlp_kernel(
    const float* __restrict__ W1, const float* __restrict__ W2)
{
    const int s = blockIdx.x;
    const int c = threadIdx.x;

    __shared__ float s_pooled[CHAN];
    __shared__ float s_h[HID];
    __shared__ float s_red[CHAN];

    // Reduce per-block sums for (segment s, channel c): coalesced across c
    float sum = 0.f;
    #pragma unroll 8
    for (int b = 0; b < NBLK1; b++)
        sum += g_part[(size_t)b * (NUM_SEG * CHAN) + s * CHAN + c];

    // Reduce counts (thread-strided + shared tree)
    float cacc = 0.f;
    for (int b = c; b < NBLK1; b += CHAN)
        cacc += g_cntp[b * NUM_SEG + s];
    s_red[c] = cacc;
    __syncthreads();
    #pragma unroll
    for (int off = CHAN / 2; off > 0; off >>= 1) {
        if (c < off) s_red[c] += s_red[c + off];
        __syncthreads();
    }
    float cnt = fmaxf(s_red[0], 1.0f);

    s_pooled[c] = sum / cnt;
    __syncthreads();

    // h = relu(pooled @ W1^T): threads 0..31 each do one dot-128
    if (c < HID) {
        float acc = 0.f;
        #pragma unroll 8
        for (int k = 0; k < CHAN; k++)
            acc += s_pooled[k] * __ldg(W1 + c * CHAN + k);
        s_h[c] = fmaxf(acc, 0.f);
    }
    __syncthreads();

    // gate = sigmoid(h @ W2^T): all 128 threads do a dot-32
    float acc = 0.f;
    #pragma unroll
    for (int k = 0; k < HID; k++)
        acc += s_h[k] * __ldg(W2 + c * HID + k);
    g_gate[s * CHAN + c] = 1.0f / (1.0f + expf(-acc));
}

// ---------------------------------------------------------------------------
// Kernel 3: out[row][c] = x[row][c] * gate[idx[row]][c].  float4, gate in smem.
// Warp's 32 lanes cover exactly one row (32 float4 = 128 floats), so the
// indices load is a uniform broadcast.
// ---------------------------------------------------------------------------
__global__ void __launch_bounds__(THR3) modulate_kernel(
    const float* __restrict__ x, const int* __restrict__ idx,
    float* __restrict__ out, int N)
{
    __shared__ float4 s_gate[NUM_SEG * 32];  // 8KB

    for (int i = threadIdx.x; i < NUM_SEG * 32; i += THR3)
        s_gate[i] = ((const float4*)g_gate)[i];
    __syncthreads();

    const float4* X = (const float4*)x;
    float4* O = (float4*)out;
    const int total = N * 32;
    const int stride = NBLK3 * THR3;

    #pragma unroll 4
    for (int i = blockIdx.x * THR3 + threadIdx.x; i < total; i += stride) {
        int row  = i >> 5;
        int lane = i & 31;
        int s = __ldg(idx + row);
        float4 v = X[i];
        float4 g = s_gate[s * 32 + lane];
        v.x *= g.x; v.y *= g.y; v.z *= g.z; v.w *= g.w;
        O[i] = v;
    }
}

// ---------------------------------------------------------------------------
extern "C" void kernel_launch(void* const* d_in, const int* in_sizes, int n_in,
                              void* d_out, int out_size)
{
    const float* x   = (const float*)d_in[0];
    const int*   idx = (const int*)d_in[1];
    const float* W1  = (const float*)d_in[2];
    const float* W2  = (const float*)d_in[3];
    float* out = (float*)d_out;

    const int N = in_sizes[1];  // number of points

    seg_sum_kernel<<<NBLK1, THR1>>>(x, idx, N);
    reduce_mlp_kernel<<<NUM_SEG, CHAN>>>(W1, W2);
    modulate_kernel<<<NBLK3, THR3>>>(x, idx, out, N);
}

// round 3
// speedup vs baseline: 1.0194x; 1.0194x over previous
#include <cuda_runtime.h>
#include <cuda_bf16.h>
#include <math.h>

#define NUM_SEG 16
#define CHAN 128
#define HID 32

// Pass-1: 256 thr (8 warps), 32KB smem -> 7 blocks/SM, 56 warps/SM
#define NBLK1 1036
#define THR1 256

// Modulate grid
#define NBLK3 1184
#define THR3 256

__device__ float g_part[(size_t)NBLK1 * NUM_SEG * CHAN];  // per-block partial sums
__device__ float g_cntp[NBLK1 * NUM_SEG];                 // per-block partial counts
__device__ float g_gate[NUM_SEG * CHAN];                  // final gates

// ---- packed f32x2 helpers (sm_103a) --------------------------------------
__device__ __forceinline__ unsigned long long fadd2(unsigned long long a,
                                                    unsigned long long b) {
    unsigned long long r;
    asm("add.rn.f32x2 %0, %1, %2;" : "=l"(r) : "l"(a), "l"(b));
    return r;
}
__device__ __forceinline__ unsigned long long fmul2(unsigned long long a,
                                                    unsigned long long b) {
    unsigned long long r;
    asm("mul.rn.f32x2 %0, %1, %2;" : "=l"(r) : "l"(a), "l"(b));
    return r;
}

// ---------------------------------------------------------------------------
// Kernel 1: segment sums. A warp PAIR shares each row: warp half h = w&1 owns
// channels [h*64, h*64+64). Each lane RMWs one float2 in its 4KB private
// region (16 seg x 32 float2), non-atomic. Counts in registers on even warps.
// ---------------------------------------------------------------------------
__global__ void __launch_bounds__(THR1) seg_sum_kernel(
    const float* __restrict__ x, const int* __restrict__ idx, int N)
{
    __shared__ unsigned long long s_acc[8 * NUM_SEG * 32];  // 8 x 4KB = 32KB
    __shared__ float s_cnt[4 * NUM_SEG];

    const int tid  = threadIdx.x;
    const int lane = tid & 31;
    const int w    = tid >> 5;
    const int h    = w & 1;                     // channel half

    unsigned long long* buf = s_acc + w * (NUM_SEG * 32);

    for (int i = tid; i < 8 * NUM_SEG * 32; i += THR1)
        s_acc[i] = 0ull;
    __syncthreads();

    const int pair = blockIdx.x * 4 + (w >> 1);  // global pair id
    const int np   = NBLK1 * 4;                  // total pairs
    // x viewed as u64 (float2); this warp's element within a row:
    const unsigned long long* X = (const unsigned long long*)x;
    const int coloff = h * 32 + lane;

    int cnt = 0;
    int r = pair;
    for (; r + 3 * np < N; r += 4 * np) {
        int s0 = __ldg(idx + r);
        int s1 = __ldg(idx + r + np);
        int s2 = __ldg(idx + r + 2 * np);
        int s3 = __ldg(idx + r + 3 * np);
        unsigned long long v0 = __ldcs(X + (size_t)r * 64 + coloff);
        unsigned long long v1 = __ldcs(X + (size_t)(r + np) * 64 + coloff);
        unsigned long long v2 = __ldcs(X + (size_t)(r + 2 * np) * 64 + coloff);
        unsigned long long v3 = __ldcs(X + (size_t)(r + 3 * np) * 64 + coloff);
        cnt += (s0 == lane) + (s1 == lane) + (s2 == lane) + (s3 == lane);

        unsigned long long* p;
        p = buf + s0 * 32 + lane; *p = fadd2(*p, v0);
        p = buf + s1 * 32 + lane; *p = fadd2(*p, v1);
        p = buf + s2 * 32 + lane; *p = fadd2(*p, v2);
        p = buf + s3 * 32 + lane; *p = fadd2(*p, v3);
    }
    for (; r < N; r += np) {
        int s = __ldg(idx + r);
        unsigned long long v = __ldcs(X + (size_t)r * 64 + coloff);
        cnt += (s == lane);
        unsigned long long* p = buf + s * 32 + lane;
        *p = fadd2(*p, v);
    }

    if (h == 0 && lane < NUM_SEG) s_cnt[(w >> 1) * NUM_SEG + lane] = (float)cnt;
    __syncthreads();

    // Combine the 4 regions per channel-half -> per-block partials in GMEM.
    // g_part as u64: [block][seg][64]; element j = half*32 + p covers
    // channels (j*2, j*2+1).
    const int RW = NUM_SEG * 32;  // u64 elements per warp region (512)
    for (int i = tid; i < NUM_SEG * 64; i += THR1) {
        int seg  = i >> 6;
        int j    = i & 63;
        int half = j >> 5;
        int p    = j & 31;
        unsigned long long v = s_acc[half * RW + seg * 32 + p];
        v = fadd2(v, s_acc[(half + 2) * RW + seg * 32 + p]);
        v = fadd2(v, s_acc[(half + 4) * RW + seg * 32 + p]);
        v = fadd2(v, s_acc[(half + 6) * RW + seg * 32 + p]);
        ((unsigned long long*)g_part)[(size_t)blockIdx.x * (NUM_SEG * 64) + i] = v;
    }
    if (tid < NUM_SEG) {
        g_cntp[blockIdx.x * NUM_SEG + tid] =
            s_cnt[tid] + s_cnt[NUM_SEG + tid] +
            s_cnt[2 * NUM_SEG + tid] + s_cnt[3 * NUM_SEG + tid];
    }
}

// ---------------------------------------------------------------------------
// Kernel 2: reduce partials + SE MLP. Grid = 16 blocks, 512 threads:
// 4-way split over the NBLK1 partials for MLP, then tiny MLP.
// ---------------------------------------------------------------------------
__global__ void __launch_bounds__(512) reduce_mlp_kernel(
    const float* __restrict__ W1, const float* __restrict__ W2)
{
    const int s    = blockIdx.x;
    const int tid  = threadIdx.x;
    const int c    = tid & (CHAN - 1);
    const int part = tid >> 7;  // 0..3

    __shared__ float red[512];
    __shared__ float s_pooled[CHAN];
    __shared__ float s_h[HID];

    // counts
    float cacc = 0.f;
    for (int b = tid; b < NBLK1; b += 512)
        cacc += g_cntp[b * NUM_SEG + s];
    red[tid] = cacc;
    __syncthreads();
    #pragma unroll
    for (int off = 256; off > 0; off >>= 1) {
        if (tid < off) red[tid] += red[tid + off];
        __syncthreads();
    }
    float cnt = fmaxf(red[0], 1.0f);
    __syncthreads();

    // sums: 4 threads per channel split the block range
    float sum = 0.f;
    #pragma unroll 8
    for (int b = part; b < NBLK1; b += 4)
        sum += g_part[(size_t)b * (NUM_SEG * CHAN) + s * CHAN + c];
    red[tid] = sum;
    __syncthreads();
    if (tid < CHAN)
        s_pooled[tid] = (red[tid] + red[tid + 128] + red[tid + 256] + red[tid + 384]) / cnt;
    __syncthreads();

    if (tid < HID) {
        float acc = 0.f;
        #pragma unroll 8
        for (int k = 0; k < CHAN; k++)
            acc += s_pooled[k] * __ldg(W1 + tid * CHAN + k);
        s_h[tid] = fmaxf(acc, 0.f);
    }
    __syncthreads();

    if (tid < CHAN) {
        float acc = 0.f;
        #pragma unroll
        for (int k = 0; k < HID; k++)
            acc += s_h[k] * __ldg(W2 + tid * HID + k);
        g_gate[s * CHAN + tid] = 1.0f / (1.0f + expf(-acc));
    }
}

// ---------------------------------------------------------------------------
// Kernel 3: out = x * gate[idx]. float4 + packed f32x2 muls, streaming hints.
// Warp's 32 lanes cover exactly one row, so idx load is a uniform broadcast.
// ---------------------------------------------------------------------------
__global__ void __launch_bounds__(THR3) modulate_kernel(
    const float* __restrict__ x, const int* __restrict__ idx,
    float* __restrict__ out, int N)
{
    __shared__ float4 s_gate[NUM_SEG * 32];  // 8KB

    for (int i = threadIdx.x; i < NUM_SEG * 32; i += THR3)
        s_gate[i] = ((const float4*)g_gate)[i];
    __syncthreads();

    const float4* X = (const float4*)x;
    float4* O = (float4*)out;
    const int total  = N * 32;
    const int stride = NBLK3 * THR3;

    #pragma unroll 4
    for (int i = blockIdx.x * THR3 + threadIdx.x; i < total; i += stride) {
        int row  = i >> 5;
        int lane = i & 31;
        int s = __ldg(idx + row);
        float4 v = __ldcs(X + i);
        float4 g = s_gate[s * 32 + lane];
        unsigned long long* vp = (unsigned long long*)&v;
        const unsigned long long* gp = (const unsigned long long*)&g;
        vp[0] = fmul2(vp[0], gp[0]);
        vp[1] = fmul2(vp[1], gp[1]);
        __stcs(O + i, v);
    }
}

// ---------------------------------------------------------------------------
extern "C" void kernel_launch(void* const* d_in, const int* in_sizes, int n_in,
                              void* d_out, int out_size)
{
    const float* x   = (const float*)d_in[0];
    const int*   idx = (const int*)d_in[1];
    const float* W1  = (const float*)d_in[2];
    const float* W2  = (const float*)d_in[3];
    float* out = (float*)d_out;

    const int N = in_sizes[1];  // number of points

    seg_sum_kernel<<<NBLK1, THR1>>>(x, idx, N);
    reduce_mlp_kernel<<<NUM_SEG, 512>>>(W1, W2);
    modulate_kernel<<<NBLK3, THR3>>>(x, idx, out, N);
}

// round 4
// speedup vs baseline: 1.1698x; 1.1476x over previous
#include <cuda_runtime.h>
#include <cuda_bf16.h>
#include <math.h>

#define NUM_SEG 16
#define CHAN 128
#define HID 32

// Pass-1: 128 thr (4 warps), 32KB smem -> 7 blocks/SM
#define NBLK1 1036
#define THR1 128

// Modulate grid
#define NBLK3 1184
#define THR3 256

__device__ float g_part[(size_t)NBLK1 * NUM_SEG * CHAN];  // per-block partial sums
__device__ float g_cntp[NBLK1 * NUM_SEG];                 // per-block partial counts
__device__ float g_gate[NUM_SEG * CHAN];                  // final gates

// ---- packed f32x2 helpers (sm_103a) --------------------------------------
__device__ __forceinline__ unsigned long long fadd2(unsigned long long a,
                                                    unsigned long long b) {
    unsigned long long r;
    asm("add.rn.f32x2 %0, %1, %2;" : "=l"(r) : "l"(a), "l"(b));
    return r;
}
__device__ __forceinline__ unsigned long long fmul2(unsigned long long a,
                                                    unsigned long long b) {
    unsigned long long r;
    asm("mul.rn.f32x2 %0, %1, %2;" : "=l"(r) : "l"(a), "l"(b));
    return r;
}

struct F4 { unsigned long long lo, hi; };  // float4 as 2x f32x2

__device__ __forceinline__ void rmw(F4* buf, int s, int lane, F4 v) {
    F4* p = buf + s * 32 + lane;
    F4 a = *p;
    a.lo = fadd2(a.lo, v.lo);
    a.hi = fadd2(a.hi, v.hi);
    *p = a;
}

// ---------------------------------------------------------------------------
// Kernel 1: segment sums. Warp owns full rows (float4/lane), 8KB private smem
// region per warp (16 seg x 32 float4), non-atomic RMW. 8 consecutive rows
// per iteration: indices come from TWO uniform int4 LDGs (amortized ~1
// cyc/row of LSU issue), all 8 x-loads front-batched (MLP=8).
// ---------------------------------------------------------------------------
__global__ void __launch_bounds__(THR1) seg_sum_kernel(
    const float* __restrict__ x, const int* __restrict__ idx, int N)
{
    __shared__ F4 s_acc[4 * NUM_SEG * 32];   // 32KB
    __shared__ float s_cnt[4 * NUM_SEG];

    const int tid  = threadIdx.x;
    const int lane = tid & 31;
    const int w    = tid >> 5;

    F4* buf = s_acc + w * (NUM_SEG * 32);

    for (int i = tid; i < 4 * NUM_SEG * 32; i += THR1) {
        s_acc[i].lo = 0ull; s_acc[i].hi = 0ull;
    }
    __syncthreads();

    const int gw = blockIdx.x * 4 + w;   // global warp id
    const int NW = NBLK1 * 4;            // total warps
    const F4* X = (const F4*)x;
    const int ngroups = N >> 3;          // groups of 8 rows (N % 8 == 0 for 1e6)

    int cnt = 0;
    for (int g = gw; g < ngroups; g += NW) {
        const int base = g << 3;
        int4 i0 = __ldg((const int4*)(idx + base));
        int4 i1 = __ldg((const int4*)(idx + base + 4));
        F4 v0 = ((const F4*)__builtin_assume_aligned(X, 16))[(size_t)(base + 0) * 32 + lane];
        F4 v1 = X[(size_t)(base + 1) * 32 + lane];
        F4 v2 = X[(size_t)(base + 2) * 32 + lane];
        F4 v3 = X[(size_t)(base + 3) * 32 + lane];
        F4 v4 = X[(size_t)(base + 4) * 32 + lane];
        F4 v5 = X[(size_t)(base + 5) * 32 + lane];
        F4 v6 = X[(size_t)(base + 6) * 32 + lane];
        F4 v7 = X[(size_t)(base + 7) * 32 + lane];

        cnt += (i0.x == lane) + (i0.y == lane) + (i0.z == lane) + (i0.w == lane)
             + (i1.x == lane) + (i1.y == lane) + (i1.z == lane) + (i1.w == lane);

        rmw(buf, i0.x, lane, v0);
        rmw(buf, i0.y, lane, v1);
        rmw(buf, i0.z, lane, v2);
        rmw(buf, i0.w, lane, v3);
        rmw(buf, i1.x, lane, v4);
        rmw(buf, i1.y, lane, v5);
        rmw(buf, i1.z, lane, v6);
        rmw(buf, i1.w, lane, v7);
    }
    // tail (N not multiple of 8): handled row-by-row
    for (int r = (ngroups << 3) + gw; r < N; r += NW) {
        int s = __ldg(idx + r);
        F4 v = X[(size_t)r * 32 + lane];
        cnt += (s == lane);
        rmw(buf, s, lane, v);
    }

    if (lane < NUM_SEG) s_cnt[w * NUM_SEG + lane] = (float)cnt;
    __syncthreads();

    // Combine 4 warp regions -> per-block partials in GMEM (u64 view).
    const unsigned long long* sa = (const unsigned long long*)s_acc;
    const int R = NUM_SEG * 64;  // u64 elements per region (1024)
    for (int i = tid; i < R; i += THR1) {
        unsigned long long v = sa[i];
        v = fadd2(v, sa[R + i]);
        v = fadd2(v, sa[2 * R + i]);
        v = fadd2(v, sa[3 * R + i]);
        ((unsigned long long*)g_part)[(size_t)blockIdx.x * R + i] = v;
    }
    if (tid < NUM_SEG) {
        g_cntp[blockIdx.x * NUM_SEG + tid] =
            s_cnt[tid] + s_cnt[NUM_SEG + tid] +
            s_cnt[2 * NUM_SEG + tid] + s_cnt[3 * NUM_SEG + tid];
    }
}

// ---------------------------------------------------------------------------
// Kernel 2: reduce partials + SE MLP. Grid = 16 blocks, 512 threads.
// ---------------------------------------------------------------------------
__global__ void __launch_bounds__(512) reduce_mlp_kernel(
    const float* __restrict__ W1, const float* __restrict__ W2)
{
    const int s    = blockIdx.x;
    const int tid  = threadIdx.x;
    const int c    = tid & (CHAN - 1);
    const int part = tid >> 7;  // 0..3

    __shared__ float red[512];
    __shared__ float s_pooled[CHAN];
    __shared__ float s_h[HID];

    // counts
    float cacc = 0.f;
    for (int b = tid; b < NBLK1; b += 512)
        cacc += g_cntp[b * NUM_SEG + s];
    red[tid] = cacc;
    __syncthreads();
    #pragma unroll
    for (int off = 256; off > 0; off >>= 1) {
        if (tid < off) red[tid] += red[tid + off];
        __syncthreads();
    }
    float cnt = fmaxf(red[0], 1.0f);
    __syncthreads();

    // sums: 4 threads per channel split the block range
    float sum = 0.f;
    #pragma unroll 8
    for (int b = part; b < NBLK1; b += 4)
        sum += g_part[(size_t)b * (NUM_SEG * CHAN) + s * CHAN + c];
    red[tid] = sum;
    __syncthreads();
    if (tid < CHAN)
        s_pooled[tid] = (red[tid] + red[tid + 128] + red[tid + 256] + red[tid + 384]) / cnt;
    __syncthreads();

    if (tid < HID) {
        float acc = 0.f;
        #pragma unroll 8
        for (int k = 0; k < CHAN; k++)
            acc += s_pooled[k] * __ldg(W1 + tid * CHAN + k);
        s_h[tid] = fmaxf(acc, 0.f);
    }
    __syncthreads();

    if (tid < CHAN) {
        float acc = 0.f;
        #pragma unroll
        for (int k = 0; k < HID; k++)
            acc += s_h[k] * __ldg(W2 + tid * HID + k);
        g_gate[s * CHAN + tid] = 1.0f / (1.0f + expf(-acc));
    }
}

// ---------------------------------------------------------------------------
// Kernel 3: out = x * gate[idx]. float4 + packed f32x2 muls, streaming hints.
// Warp's 32 lanes cover exactly one row, so idx load is a uniform broadcast.
// ---------------------------------------------------------------------------
__global__ void __launch_bounds__(THR3) modulate_kernel(
    const float* __restrict__ x, const int* __restrict__ idx,
    float* __restrict__ out, int N)
{
    __shared__ float4 s_gate[NUM_SEG * 32];  // 8KB

    for (int i = threadIdx.x; i < NUM_SEG * 32; i += THR3)
        s_gate[i] = ((const float4*)g_gate)[i];
    __syncthreads();

    const float4* X = (const float4*)x;
    float4* O = (float4*)out;
    const int total  = N * 32;
    const int stride = NBLK3 * THR3;

    #pragma unroll 4
    for (int i = blockIdx.x * THR3 + threadIdx.x; i < total; i += stride) {
        int row  = i >> 5;
        int lane = i & 31;
        int s = __ldg(idx + row);
        float4 v = __ldcs(X + i);
        float4 g = s_gate[s * 32 + lane];
        unsigned long long* vp = (unsigned long long*)&v;
        const unsigned long long* gp = (const unsigned long long*)&g;
        vp[0] = fmul2(vp[0], gp[0]);
        vp[1] = fmul2(vp[1], gp[1]);
        __stcs(O + i, v);
    }
}

// ---------------------------------------------------------------------------
extern "C" void kernel_launch(void* const* d_in, const int* in_sizes, int n_in,
                              void* d_out, int out_size)
{
    const float* x   = (const float*)d_in[0];
    const int*   idx = (const int*)d_in[1];
    const float* W1  = (const float*)d_in[2];
    const float* W2  = (const float*)d_in[3];
    float* out = (float*)d_out;

    const int N = in_sizes[1];  // number of points

    seg_sum_kernel<<<NBLK1, THR1>>>(x, idx, N);
    reduce_mlp_kernel<<<NUM_SEG, 512>>>(W1, W2);
    modulate_kernel<<<NBLK3, THR3>>>(x, idx, out, N);
}

// round 5
// speedup vs baseline: 1.2916x; 1.1041x over previous
#include <cuda_runtime.h>
#include <cuda_bf16.h>
#include <math.h>

#define NUM_SEG 16
#define CHAN 128
#define HID 32

// Pass-1: 128 thr (4 warps), ~33KB smem -> 6 blocks/SM. Single full wave:
#define NBLK1 888          // 148 SMs * 6 blocks
#define THR1 128

// Modulate grid: 8 blocks/SM * 148 = one full wave
#define NBLK3 1184
#define THR3 256

__device__ float g_part[(size_t)NBLK1 * NUM_SEG * CHAN];  // per-block partial sums
__device__ float g_cntp[NBLK1 * NUM_SEG];                 // per-block partial counts
__device__ float g_gate[NUM_SEG * CHAN];                  // final gates

// ---- packed f32x2 helpers (sm_103a) --------------------------------------
__device__ __forceinline__ unsigned long long fadd2(unsigned long long a,
                                                    unsigned long long b) {
    unsigned long long r;
    asm("add.rn.f32x2 %0, %1, %2;" : "=l"(r) : "l"(a), "l"(b));
    return r;
}
__device__ __forceinline__ unsigned long long fmul2(unsigned long long a,
                                                    unsigned long long b) {
    unsigned long long r;
    asm("mul.rn.f32x2 %0, %1, %2;" : "=l"(r) : "l"(a), "l"(b));
    return r;
}

struct F4 { unsigned long long lo, hi; };  // float4 as 2x f32x2

__device__ __forceinline__ void rmw(F4* buf, int s, int lane, F4 v) {
    F4* p = buf + s * 32 + lane;
    F4 a = *p;
    a.lo = fadd2(a.lo, v.lo);
    a.hi = fadd2(a.hi, v.hi);
    *p = a;
}

// ---------------------------------------------------------------------------
// Kernel 1: segment sums. Warp owns full rows (float4/lane), 8KB private smem
// region per warp (16 seg x 32 float4), non-atomic RMW. 8 consecutive rows
// per iteration: indices from TWO uniform int4 LDGs, all 8 x-loads batched.
// Grid = exactly one resident wave (888 blocks @ 6 blocks/SM).
// ---------------------------------------------------------------------------
__global__ void __launch_bounds__(THR1) seg_sum_kernel(
    const float* __restrict__ x, const int* __restrict__ idx, int N)
{
    __shared__ F4 s_acc[4 * NUM_SEG * 32];   // 32KB
    __shared__ float s_cnt[4 * NUM_SEG];

    const int tid  = threadIdx.x;
    const int lane = tid & 31;
    const int w    = tid >> 5;

    F4* buf = s_acc + w * (NUM_SEG * 32);

    for (int i = tid; i < 4 * NUM_SEG * 32; i += THR1) {
        s_acc[i].lo = 0ull; s_acc[i].hi = 0ull;
    }
    __syncthreads();

    const int gw = blockIdx.x * 4 + w;   // global warp id
    const int NW = NBLK1 * 4;            // total warps
    const F4* X = (const F4*)x;
    const int ngroups = N >> 3;          // groups of 8 rows

    int cnt = 0;
    for (int g = gw; g < ngroups; g += NW) {
        const int base = g << 3;
        int4 i0 = __ldg((const int4*)(idx + base));
        int4 i1 = __ldg((const int4*)(idx + base + 4));
        F4 v0 = X[(size_t)(base + 0) * 32 + lane];
        F4 v1 = X[(size_t)(base + 1) * 32 + lane];
        F4 v2 = X[(size_t)(base + 2) * 32 + lane];
        F4 v3 = X[(size_t)(base + 3) * 32 + lane];
        F4 v4 = X[(size_t)(base + 4) * 32 + lane];
        F4 v5 = X[(size_t)(base + 5) * 32 + lane];
        F4 v6 = X[(size_t)(base + 6) * 32 + lane];
        F4 v7 = X[(size_t)(base + 7) * 32 + lane];

        cnt += (i0.x == lane) + (i0.y == lane) + (i0.z == lane) + (i0.w == lane)
             + (i1.x == lane) + (i1.y == lane) + (i1.z == lane) + (i1.w == lane);

        rmw(buf, i0.x, lane, v0);
        rmw(buf, i0.y, lane, v1);
        rmw(buf, i0.z, lane, v2);
        rmw(buf, i0.w, lane, v3);
        rmw(buf, i1.x, lane, v4);
        rmw(buf, i1.y, lane, v5);
        rmw(buf, i1.z, lane, v6);
        rmw(buf, i1.w, lane, v7);
    }
    // tail (N not multiple of 8)
    for (int r = (ngroups << 3) + gw; r < N; r += NW) {
        int s = __ldg(idx + r);
        F4 v = X[(size_t)r * 32 + lane];
        cnt += (s == lane);
        rmw(buf, s, lane, v);
    }

    if (lane < NUM_SEG) s_cnt[w * NUM_SEG + lane] = (float)cnt;
    __syncthreads();

    // Combine 4 warp regions -> per-block partials in GMEM (u64 view).
    const unsigned long long* sa = (const unsigned long long*)s_acc;
    const int R = NUM_SEG * 64;  // u64 elements per region (1024)
    for (int i = tid; i < R; i += THR1) {
        unsigned long long v = sa[i];
        v = fadd2(v, sa[R + i]);
        v = fadd2(v, sa[2 * R + i]);
        v = fadd2(v, sa[3 * R + i]);
        ((unsigned long long*)g_part)[(size_t)blockIdx.x * R + i] = v;
    }
    if (tid < NUM_SEG) {
        g_cntp[blockIdx.x * NUM_SEG + tid] =
            s_cnt[tid] + s_cnt[NUM_SEG + tid] +
            s_cnt[2 * NUM_SEG + tid] + s_cnt[3 * NUM_SEG + tid];
    }
}

// ---------------------------------------------------------------------------
// Kernel 2: reduce partials + SE MLP. Grid = 16 blocks, 1024 threads:
// 8-way split over the NBLK1 partials per channel, then tiny MLP.
// ---------------------------------------------------------------------------
__global__ void __launch_bounds__(1024) reduce_mlp_kernel(
    const float* __restrict__ W1, const float* __restrict__ W2)
{
    const int s    = blockIdx.x;
    const int tid  = threadIdx.x;
    const int c    = tid & (CHAN - 1);
    const int part = tid >> 7;  // 0..7

    __shared__ float red[1024];
    __shared__ float s_pooled[CHAN];
    __shared__ float s_h[HID];

    // counts
    float cacc = 0.f;
    for (int b = tid; b < NBLK1; b += 1024)
        cacc += g_cntp[b * NUM_SEG + s];
    red[tid] = cacc;
    __syncthreads();
    #pragma unroll
    for (int off = 512; off > 0; off >>= 1) {
        if (tid < off) red[tid] += red[tid + off];
        __syncthreads();
    }
    float cnt = fmaxf(red[0], 1.0f);
    __syncthreads();

    // sums: 8 threads per channel split the block range
    float sum = 0.f;
    #pragma unroll 8
    for (int b = part; b < NBLK1; b += 8)
        sum += g_part[(size_t)b * (NUM_SEG * CHAN) + s * CHAN + c];
    red[tid] = sum;
    __syncthreads();
    if (tid < CHAN) {
        float v = 0.f;
        #pragma unroll
        for (int p = 0; p < 8; p++) v += red[p * 128 + tid];
        s_pooled[tid] = v / cnt;
    }
    __syncthreads();

    if (tid < HID) {
        float acc = 0.f;
        #pragma unroll 8
        for (int k = 0; k < CHAN; k++)
            acc += s_pooled[k] * __ldg(W1 + tid * CHAN + k);
        s_h[tid] = fmaxf(acc, 0.f);
    }
    __syncthreads();

    if (tid < CHAN) {
        float acc = 0.f;
        #pragma unroll
        for (int k = 0; k < HID; k++)
            acc += s_h[k] * __ldg(W2 + tid * HID + k);
        g_gate[s * CHAN + tid] = 1.0f / (1.0f + expf(-acc));
    }
}

// ---------------------------------------------------------------------------
// Kernel 3: out = x * gate[idx]. float4 + packed f32x2 muls, streaming hints.
// Warp's 32 lanes cover exactly one row, so idx load is a uniform broadcast.
// ---------------------------------------------------------------------------
__global__ void __launch_bounds__(THR3) modulate_kernel(
    const float* __restrict__ x, const int* __restrict__ idx,
    float* __restrict__ out, int N)
{
    __shared__ float4 s_gate[NUM_SEG * 32];  // 8KB

    for (int i = threadIdx.x; i < NUM_SEG * 32; i += THR3)
        s_gate[i] = ((const float4*)g_gate)[i];
    __syncthreads();

    const float4* X = (const float4*)x;
    float4* O = (float4*)out;
    const int total  = N * 32;
    const int stride = NBLK3 * THR3;

    #pragma unroll 4
    for (int i = blockIdx.x * THR3 + threadIdx.x; i < total; i += stride) {
        int row  = i >> 5;
        int lane = i & 31;
        int s = __ldg(idx + row);
        float4 v = __ldcs(X + i);
        float4 g = s_gate[s * 32 + lane];
        unsigned long long* vp = (unsigned long long*)&v;
        const unsigned long long* gp = (const unsigned long long*)&g;
        vp[0] = fmul2(vp[0], gp[0]);
        vp[1] = fmul2(vp[1], gp[1]);
        __stcs(O + i, v);
    }
}

// ---------------------------------------------------------------------------
extern "C" void kernel_launch(void* const* d_in, const int* in_sizes, int n_in,
                              void* d_out, int out_size)
{
    const float* x   = (const float*)d_in[0];
    const int*   idx = (const int*)d_in[1];
    const float* W1  = (const float*)d_in[2];
    const float* W2  = (const float*)d_in[3];
    float* out = (float*)d_out;

    const int N = in_sizes[1];  // number of points

    seg_sum_kernel<<<NBLK1, THR1>>>(x, idx, N);
    reduce_mlp_kernel<<<NUM_SEG, 1024>>>(W1, W2);
    modulate_kernel<<<NBLK3, THR3>>>(x, idx, out, N);
}

// round 6
// speedup vs baseline: 1.2959x; 1.0034x over previous
#include <cuda_runtime.h>
#include <cuda_bf16.h>
#include <math.h>

#define NUM_SEG 16
#define CHAN 128
#define HID 32

// Pass-1: 128 thr (4 warps), ~33KB smem -> 6 blocks/SM. Single full wave.
#define NBLK1 888          // 148 SMs * 6 blocks
#define THR1 128

// Modulate grid: 8 blocks/SM * 148 = one full wave
#define NBLK3 1184
#define THR3 256

__device__ float g_part[(size_t)NBLK1 * NUM_SEG * CHAN];  // per-block partial sums
__device__ float g_cntp[NBLK1 * NUM_SEG];                 // per-block partial counts
__device__ float g_gate[NUM_SEG * CHAN];                  // final gates

// ---- packed f32x2 helpers (sm_103a) --------------------------------------
__device__ __forceinline__ unsigned long long fadd2(unsigned long long a,
                                                    unsigned long long b) {
    unsigned long long r;
    asm("add.rn.f32x2 %0, %1, %2;" : "=l"(r) : "l"(a), "l"(b));
    return r;
}
__device__ __forceinline__ unsigned long long fmul2(unsigned long long a,
                                                    unsigned long long b) {
    unsigned long long r;
    asm("mul.rn.f32x2 %0, %1, %2;" : "=l"(r) : "l"(a), "l"(b));
    return r;
}

struct F4 { unsigned long long lo, hi; };  // float4 as 2x f32x2

__device__ __forceinline__ F4 ld_f4_cs(const F4* p) {
    F4 r;
    asm("ld.global.cs.v4.b32 {%0,%1,%2,%3}, [%4];"
        : "=r"(((unsigned*)&r)[0]), "=r"(((unsigned*)&r)[1]),
          "=r"(((unsigned*)&r)[2]), "=r"(((unsigned*)&r)[3])
        : "l"(p));
    return r;
}

__device__ __forceinline__ void rmw(F4* buf, int s, int lane, F4 v) {
    F4* p = buf + s * 32 + lane;
    F4 a = *p;
    a.lo = fadd2(a.lo, v.lo);
    a.hi = fadd2(a.hi, v.hi);
    *p = a;
}

// ---------------------------------------------------------------------------
// Kernel 1: segment sums. Warp owns full rows (float4/lane), 8KB private smem
// region per warp, non-atomic RMW. 8 rows/iteration with a STAGGERED
// SOFTWARE PIPELINE: next group's loads are issued before/between the current
// group's smem RMWs, so DRAM requests stay in flight through the RMW window.
// ---------------------------------------------------------------------------
__global__ void __launch_bounds__(THR1, 6) seg_sum_kernel(
    const float* __restrict__ x, const int* __restrict__ idx, int N)
{
    __shared__ F4 s_acc[4 * NUM_SEG * 32];   // 32KB
    __shared__ float s_cnt[4 * NUM_SEG];

    const int tid  = threadIdx.x;
    const int lane = tid & 31;
    const int w    = tid >> 5;

    F4* buf = s_acc + w * (NUM_SEG * 32);

    for (int i = tid; i < 4 * NUM_SEG * 32; i += THR1) {
        s_acc[i].lo = 0ull; s_acc[i].hi = 0ull;
    }
    __syncthreads();

    const int gw = blockIdx.x * 4 + w;   // global warp id
    const int NW = NBLK1 * 4;            // total warps
    const F4* X = (const F4*)x;
    const int ngroups = N >> 3;          // groups of 8 rows

    int cnt = 0;

    int4 ia, ib;
    F4 v0, v1, v2, v3, v4, v5, v6, v7;

    if (gw < ngroups) {
        const int base = gw << 3;
        ia = __ldg((const int4*)(idx + base));
        ib = __ldg((const int4*)(idx + base + 4));
        const size_t o = (size_t)base * 32 + lane;
        v0 = ld_f4_cs(X + o);
        v1 = ld_f4_cs(X + o + 32);
        v2 = ld_f4_cs(X + o + 64);
        v3 = ld_f4_cs(X + o + 96);
        v4 = ld_f4_cs(X + o + 128);
        v5 = ld_f4_cs(X + o + 160);
        v6 = ld_f4_cs(X + o + 192);
        v7 = ld_f4_cs(X + o + 224);
    }

    for (int g = gw; g < ngroups; g += NW) {
        // next group (clamped to current on last iter: harmless reload)
        const int gn = (g + NW < ngroups) ? g + NW : g;
        const int bn = gn << 3;
        const size_t on = (size_t)bn * 32 + lane;

        int4 na = __ldg((const int4*)(idx + bn));
        int4 nb = __ldg((const int4*)(idx + bn + 4));
        F4 n0 = ld_f4_cs(X + on);
        F4 n1 = ld_f4_cs(X + on + 32);
        F4 n2 = ld_f4_cs(X + on + 64);
        F4 n3 = ld_f4_cs(X + on + 96);

        cnt += (ia.x == lane) + (ia.y == lane) + (ia.z == lane) + (ia.w == lane)
             + (ib.x == lane) + (ib.y == lane) + (ib.z == lane) + (ib.w == lane);

        rmw(buf, ia.x, lane, v0);
        rmw(buf, ia.y, lane, v1);
        rmw(buf, ia.z, lane, v2);
        rmw(buf, ia.w, lane, v3);

        F4 n4 = ld_f4_cs(X + on + 128);
        F4 n5 = ld_f4_cs(X + on + 160);
        F4 n6 = ld_f4_cs(X + on + 192);
        F4 n7 = ld_f4_cs(X + on + 224);

        rmw(buf, ib.x, lane, v4);
        rmw(buf, ib.y, lane, v5);
        rmw(buf, ib.z, lane, v6);
        rmw(buf, ib.w, lane, v7);

        ia = na; ib = nb;
        v0 = n0; v1 = n1; v2 = n2; v3 = n3;
        v4 = n4; v5 = n5; v6 = n6; v7 = n7;
    }
    // NOTE: the loop RMWs each group exactly once (the last iteration's
    // prefetch is a dead reload of the same group).

    // tail (N not multiple of 8)
    for (int r = (ngroups << 3) + gw; r < N; r += NW) {
        int s = __ldg(idx + r);
        F4 v = ld_f4_cs(X + (size_t)r * 32 + lane);
        cnt += (s == lane);
        rmw(buf, s, lane, v);
    }

    if (lane < NUM_SEG) s_cnt[w * NUM_SEG + lane] = (float)cnt;
    __syncthreads();

    // Combine 4 warp regions -> per-block partials in GMEM (u64 view).
    const unsigned long long* sa = (const unsigned long long*)s_acc;
    const int R = NUM_SEG * 64;  // u64 elements per region (1024)
    for (int i = tid; i < R; i += THR1) {
        unsigned long long v = sa[i];
        v = fadd2(v, sa[R + i]);
        v = fadd2(v, sa[2 * R + i]);
        v = fadd2(v, sa[3 * R + i]);
        ((unsigned long long*)g_part)[(size_t)blockIdx.x * R + i] = v;
    }
    if (tid < NUM_SEG) {
        g_cntp[blockIdx.x * NUM_SEG + tid] =
            s_cnt[tid] + s_cnt[NUM_SEG + tid] +
            s_cnt[2 * NUM_SEG + tid] + s_cnt[3 * NUM_SEG + tid];
    }
}

// ---------------------------------------------------------------------------
// Kernel 2: reduce partials + SE MLP. Grid = 16 blocks, 1024 threads.
// ---------------------------------------------------------------------------
__global__ void __launch_bounds__(1024) reduce_mlp_kernel(
    const float* __restrict__ W1, const float* __restrict__ W2)
{
    const int s    = blockIdx.x;
    const int tid  = threadIdx.x;
    const int c    = tid & (CHAN - 1);
    const int part = tid >> 7;  // 0..7

    __shared__ float red[1024];
    __shared__ float s_pooled[CHAN];
    __shared__ float s_h[HID];

    // counts
    float cacc = 0.f;
    for (int b = tid; b < NBLK1; b += 1024)
        cacc += g_cntp[b * NUM_SEG + s];
    red[tid] = cacc;
    __syncthreads();
    #pragma unroll
    for (int off = 512; off > 0; off >>= 1) {
        if (tid < off) red[tid] += red[tid + off];
        __syncthreads();
    }
    float cnt = fmaxf(red[0], 1.0f);
    __syncthreads();

    // sums: 8 threads per channel split the block range
    float sum = 0.f;
    #pragma unroll 8
    for (int b = part; b < NBLK1; b += 8)
        sum += g_part[(size_t)b * (NUM_SEG * CHAN) + s * CHAN + c];
    red[tid] = sum;
    __syncthreads();
    if (tid < CHAN) {
        float v = 0.f;
        #pragma unroll
        for (int p = 0; p < 8; p++) v += red[p * 128 + tid];
        s_pooled[tid] = v / cnt;
    }
    __syncthreads();

    if (tid < HID) {
        float acc = 0.f;
        #pragma unroll 8
        for (int k = 0; k < CHAN; k++)
            acc += s_pooled[k] * __ldg(W1 + tid * CHAN + k);
        s_h[tid] = fmaxf(acc, 0.f);
    }
    __syncthreads();

    if (tid < CHAN) {
        float acc = 0.f;
        #pragma unroll
        for (int k = 0; k < HID; k++)
            acc += s_h[k] * __ldg(W2 + tid * HID + k);
        g_gate[s * CHAN + tid] = 1.0f / (1.0f + expf(-acc));
    }
}

// ---------------------------------------------------------------------------
// Kernel 3: out = x * gate[idx]. float4 + packed f32x2 muls, streaming hints.
// Warp's 32 lanes cover exactly one row, so idx load is a uniform broadcast.
// ---------------------------------------------------------------------------
__global__ void __launch_bounds__(THR3) modulate_kernel(
    const float* __restrict__ x, const int* __restrict__ idx,
    float* __restrict__ out, int N)
{
    __shared__ float4 s_gate[NUM_SEG * 32];  // 8KB

    for (int i = threadIdx.x; i < NUM_SEG * 32; i += THR3)
        s_gate[i] = ((const float4*)g_gate)[i];
    __syncthreads();

    const float4* X = (const float4*)x;
    float4* O = (float4*)out;
    const int total  = N * 32;
    const int stride = NBLK3 * THR3;

    #pragma unroll 4
    for (int i = blockIdx.x * THR3 + threadIdx.x; i < total; i += stride) {
        int row  = i >> 5;
        int lane = i & 31;
        int s = __ldg(idx + row);
        float4 v = __ldcs(X + i);
        float4 g = s_gate[s * 32 + lane];
        unsigned long long* vp = (unsigned long long*)&v;
        const unsigned long long* gp = (const unsigned long long*)&g;
        vp[0] = fmul2(vp[0], gp[0]);
        vp[1] = fmul2(vp[1], gp[1]);
        __stcs(O + i, v);
    }
}

// ---------------------------------------------------------------------------
extern "C" void kernel_launch(void* const* d_in, const int* in_sizes, int n_in,
                              void* d_out, int out_size)
{
    const float* x   = (const float*)d_in[0];
    const int*   idx = (const int*)d_in[1];
    const float* W1  = (const float*)d_in[2];
    const float* W2  = (const float*)d_in[3];
    float* out = (float*)d_out;

    const int N = in_sizes[1];  // number of points

    seg_sum_kernel<<<NBLK1, THR1>>>(x, idx, N);
    reduce_mlp_kernel<<<NUM_SEG, 1024>>>(W1, W2);
    modulate_kernel<<<NBLK3, THR3>>>(x, idx, out, N);
}